// round 5
// baseline (speedup 1.0000x reference)
#include <cuda_runtime.h>
#include <math.h>

#define BATCH   64
#define NLIST   512
#define THREADS 512
#define QSPLIT  4              // 4 blocks per row (offset-quarter split)
#define NBLK    (BATCH * QSPLIT)   // 256
#define OCHUNK  64             // offsets per block

#define LOG_EPS (-23.025850929940457f)
#define LN2F    0.6931471805599453f

__device__ float        g_partial[NBLK];
__device__ unsigned int g_count = 0;

__global__ __launch_bounds__(THREADS, 2)
void rank_loss_main(const float* __restrict__ logits,
                    const float* __restrict__ labels,
                    float* __restrict__ out) {
    __shared__ float  s_sl[NLIST];          // masked logits (rank phase)
    __shared__ float4 sA[NLIST + 256];      // {Gj, Ej, hj, labj(NaN if invalid)} + mirror
    __shared__ float  sBp[NLIST + 256];     // qd with capped packed in low 8 mantissa bits
    __shared__ float  s_invlog[52];
    __shared__ float  s_rel[52 * 32];       // replicated: [cd*32 + lane] -> conflict-free
    __shared__ float  s_red[16];
    __shared__ bool   s_last;

    const int tid  = threadIdx.x;
    const int lane = tid & 31;
    const int b    = blockIdx.x >> 2;
    const int q    = blockIdx.x & 3;

    // --- LUT setup ---
    if (tid < 52) s_invlog[tid] = tid ? (1.0f / log1pf((float)tid)) : 0.0f;
    for (int idx = tid; idx < 52 * 32; idx += THREADS) {
        int rd = idx >> 5;
        s_rel[idx] = rd ? 0.75f * fabsf(1.0f / log1pf((float)rd)
                                      - 1.0f / log1pf((float)(rd + 1)))
                        : 0.0f;
    }

    // --- per-element load / masking ---
    const float g_raw   = logits[b * NLIST + tid];
    const float lab_raw = labels[b * NLIST + tid];
    const bool  valid   = lab_raw > -1000.0f;
    const float lab     = valid ? lab_raw : 0.0f;
    const float g       = valid ? g_raw : LOG_EPS;
    s_sl[tid] = g;
    __syncthreads();

    // --- rank = 1 + #{slj > sli}; ties only among invalid cluster (capped=51, disc=0
    //     either way, and those elements appear only in masked pairs) -> exact ---
    int cnt = 0;
    const float4* sl4 = (const float4*)s_sl;
    #pragma unroll 8
    for (int j4 = 0; j4 < NLIST / 4; ++j4) {
        float4 v = sl4[j4];
        cnt += (v.x > g);
        cnt += (v.y > g);
        cnt += (v.z > g);
        cnt += (v.w > g);
    }
    const int   rank   = cnt + 1;
    const int   capped = min(rank, 51);
    const float disc   = (rank <= 50) ? s_invlog[rank] : 0.0f;

    // --- per-element precompute ---
    const float Gi   = __expf(0.5f * g);     // exp(logit/2)
    const float Ei   = __expf(0.5f * lab);   // exp(label/2)
    const float hi   = 0.5f * g;
    const float nhi  = -hi;
    const float qdi  = 0.25f * disc;
    const float qnan = __int_as_float(0x7fffffff);
    const float labi = valid ? lab : qnan;   // NaN: |diff|>0 false -> pair inactive

    // pack capped into low 8 mantissa bits of qd (rel perturbation < 2^-15)
    const unsigned qbits = (__float_as_uint(qdi) & ~0xFFu) | (unsigned)capped;
    const float4 Av = make_float4(Gi, Ei, hi, labi);
    sA[tid]  = Av;
    sBp[tid] = __uint_as_float(qbits);
    if (tid < 256) { sA[NLIST + tid] = Av; sBp[NLIST + tid] = __uint_as_float(qbits); }
    __syncthreads();

    // --- per-row IDCG (thread 0; first 50 positions, validity via NaN sentinel) ---
    float idcg = 0.0f;
    if (tid == 0) {
        float s = 0.0f;
        #pragma unroll
        for (int p = 1; p <= 50; ++p)
            if (sA[p - 1].w < 1e30f) s += s_invlog[p];   // NaN -> false
        idcg = (s > 0.0f) ? (1.0f / s) : 0.0f;
    }

    // --- unordered-pair loop. Orientation-free identity:
    //     bce = ln2*lg2(Gi+Gj) - hi + dh*Ej/(Ei+Ej)   (both orientations)
    //     mask: |labi-labj| > 0 (NaN-safe). Offsets 1..256 quartered across blocks;
    //     offset 256 double-covered -> gate tid<256. ---
    const float* relbase = s_rel + lane;
    const int    o0      = 1 + (q << 6);
    const float4* pA = sA  + tid + o0;
    const float*  pB = sBp + tid + o0;

    float acc0 = 0.0f, acc1 = 0.0f;
    #pragma unroll 16
    for (int oo = 0; oo < OCHUNK - 1; ++oo) {
        const float4 A   = pA[oo];
        const float  Bp  = pB[oo];
        const float  t2  = __fdividef(A.y, Ei + A.y);     // Ej / (Ei+Ej)
        const float  lg  = __log2f(Gi + A.x);
        const float  dh  = hi - A.z;
        const float  core = fmaf(lg, LN2F, nhi);
        const float  bce  = fmaf(dh, t2, core);
        const float  dl   = labi - A.w;                   // NaN if either invalid
        const int    cj   = (int)(__float_as_uint(Bp) & 0xFFu);
        const int    cd   = abs(capped - cj);
        float w = relbase[cd << 5] + fabsf(qdi - Bp);
        w = (fabsf(dl) > 0.0f) ? w : 0.0f;
        if (oo & 1) acc1 = fmaf(bce, w, acc1);
        else        acc0 = fmaf(bce, w, acc0);
    }
    {   // final offset of this quarter; q==3 hits offset 256 (double-covered) -> gate
        const float4 A   = pA[OCHUNK - 1];
        const float  Bp  = pB[OCHUNK - 1];
        const bool   gate = (q != 3) | (tid < 256);
        const float  t2  = __fdividef(A.y, Ei + A.y);
        const float  lg  = __log2f(Gi + A.x);
        const float  dh  = hi - A.z;
        const float  core = fmaf(lg, LN2F, nhi);
        const float  bce  = fmaf(dh, t2, core);
        const float  dl   = labi - A.w;
        const int    cj   = (int)(__float_as_uint(Bp) & 0xFFu);
        const int    cd   = abs(capped - cj);
        float w = relbase[cd << 5] + fabsf(qdi - Bp);
        w = (gate && fabsf(dl) > 0.0f) ? w : 0.0f;
        acc0 = fmaf(bce, w, acc0);
    }
    float acc = acc0 + acc1;

    // --- deterministic block reduce + fused final reduce ---
    #pragma unroll
    for (int o = 16; o; o >>= 1) acc += __shfl_down_sync(0xffffffffu, acc, o);
    if (lane == 0) s_red[tid >> 5] = acc;
    __syncthreads();
    if (tid < 16) {
        float v = s_red[tid];
        #pragma unroll
        for (int o = 8; o; o >>= 1) v += __shfl_down_sync(0xffffu, v, o);
        if (tid == 0) {
            g_partial[blockIdx.x] = v * idcg * (1.0f / (float)BATCH);
            __threadfence();
            unsigned int old = atomicInc(&g_count, NBLK - 1);  // wraps -> replay-safe
            s_last = (old == NBLK - 1);
        }
    }
    __syncthreads();

    if (s_last) {
        __threadfence();
        if (tid < NBLK) {
            float v = ((volatile float*)g_partial)[tid];
            #pragma unroll
            for (int o = 16; o; o >>= 1) v += __shfl_down_sync(0xffffffffu, v, o);
            if (lane == 0) s_red[tid >> 5] = v;
        }
        __syncthreads();
        if (tid == 0) {
            float tot = 0.0f;
            #pragma unroll
            for (int w2 = 0; w2 < NBLK / 32; ++w2) tot += s_red[w2];
            out[0] = tot;
        }
    }
}

extern "C" void kernel_launch(void* const* d_in, const int* in_sizes, int n_in,
                              void* d_out, int out_size) {
    const float* logits = (const float*)d_in[0];
    const float* labels = (const float*)d_in[1];
    float* out = (float*)d_out;
    (void)in_sizes; (void)n_in; (void)out_size;

    rank_loss_main<<<NBLK, THREADS>>>(logits, labels, out);
}

// round 6
// speedup vs baseline: 1.0767x; 1.0767x over previous
#include <cuda_runtime.h>
#include <math.h>

#define BATCH   64
#define NLIST   512
#define THREADS 512
#define NBLK    128            // 2 blocks per row (offset-halves)

#define LOG_EPS (-23.025850929940457f)
#define LN2F    0.6931471805599453f

// 1/log1p(k) for k=0..51 (k=0 slot unused, =0)
__constant__ float C_IL[52] = {
    0.0f,          1.44269504f, 0.91023923f, 0.72134752f, 0.62133493f,
    0.55811063f,   0.51389834f, 0.48089835f, 0.45511961f, 0.43429448f,
    0.41703239f,   0.40242960f, 0.38987124f, 0.37892269f, 0.36926938f,
    0.36067376f,   0.35295525f, 0.34597526f, 0.33962297f, 0.33380821f,
    0.32845724f,   0.32351538f, 0.31892891f, 0.31465802f, 0.31066747f,
    0.30692762f,   0.30341308f, 0.30010212f, 0.29697521f, 0.29401538f,
    0.29120814f,   0.28853901f, 0.28599983f, 0.28357871f, 0.28126653f,
    0.27905531f,   0.27693789f, 0.27490773f, 0.27295812f, 0.27108450f,
    0.26928330f,   0.26754748f, 0.26587369f, 0.26425870f, 0.26269878f,
    0.26119069f,   0.25973142f, 0.25831873f, 0.25694924f, 0.25562222f,
    0.25433417f,   0.25308478f
};

__device__ float        g_partial[NBLK];
__device__ unsigned int g_count = 0;

__global__ __launch_bounds__(THREADS)
void rank_loss_main(const float* __restrict__ logits,
                    const float* __restrict__ labels,
                    float* __restrict__ out) {
    __shared__ float         s_sl[NLIST];        // masked logits (rank phase, broadcast)
    __shared__ float4        sA[NLIST + 256];    // {Gj, Ej, hj, labj(NaN if invalid)} + mirror
    __shared__ unsigned char sC[NLIST + 256];    // capped rank (1..51) + mirror
    __shared__ float         s_W[52 * 52];       // w(ci,cj) full 2D weight LUT
    __shared__ float         s_red[16];
    __shared__ bool          s_last;

    const int tid   = threadIdx.x;
    const int lane  = tid & 31;
    const int b     = blockIdx.x >> 1;
    const int jhalf = blockIdx.x & 1;

    // --- W LUT fill from literal table (no runtime log1p anywhere) ---
    for (int idx = tid; idx < 52 * 52; idx += THREADS) {
        const int ci = idx / 52;
        const int cj = idx - ci * 52;
        const int rd = abs(ci - cj);
        const float rel = rd ? 0.75f * fabsf(C_IL[rd] - C_IL[rd + 1]) : 0.0f;
        const float di  = (ci >= 1 && ci <= 50) ? C_IL[ci] : 0.0f;
        const float dj  = (cj >= 1 && cj <= 50) ? C_IL[cj] : 0.0f;
        s_W[idx] = rel + 0.25f * fabsf(di - dj);
    }

    // --- per-element load / masking ---
    const float g_raw   = logits[b * NLIST + tid];
    const float lab_raw = labels[b * NLIST + tid];
    const bool  valid   = lab_raw > -1000.0f;
    const float lab     = valid ? lab_raw : 0.0f;
    const float g       = valid ? g_raw : LOG_EPS;
    s_sl[tid] = g;
    __syncthreads();

    // --- rank = 1 + #{slj > sli}; ties only among the invalid cluster (capped=51,
    //     disc=0 either way, and those elements appear only in masked pairs) ---
    int cnt = 0;
    const float4* sl4 = (const float4*)s_sl;
    #pragma unroll 8
    for (int j4 = 0; j4 < NLIST / 4; ++j4) {
        float4 v = sl4[j4];
        cnt += (v.x > g);
        cnt += (v.y > g);
        cnt += (v.z > g);
        cnt += (v.w > g);
    }
    const int rank   = cnt + 1;
    const int capped = min(rank, 51);

    // --- per-element precompute ---
    const float Gi   = __expf(0.5f * g);     // exp(logit/2)
    const float Ei   = __expf(0.5f * lab);   // exp(label/2)
    const float hi   = 0.5f * g;
    const float nhi  = -hi;
    const float qnan = __int_as_float(0x7fffffff);
    const float labi = valid ? lab : qnan;   // NaN sentinel -> pair always inactive

    const float4 Av = make_float4(Gi, Ei, hi, labi);
    sA[tid] = Av;
    sC[tid] = (unsigned char)capped;
    if (tid < 256) { sA[NLIST + tid] = Av; sC[NLIST + tid] = (unsigned char)capped; }
    __syncthreads();

    // --- per-row IDCG (thread 0; position-based, first 50 positions) ---
    float idcg = 0.0f;
    if (tid == 0) {
        float s = 0.0f;
        #pragma unroll
        for (int p = 1; p <= 50; ++p)
            if (sA[p - 1].w < 1e30f) s += C_IL[p];   // NaN -> false -> skipped
        idcg = (s > 0.0f) ? (1.0f / s) : 0.0f;
    }

    // --- unordered-pair loop. Orientation-free identity (exact for both directions):
    //     bce = ln2*lg2(Gi+Gj) - hi + dh*Ej/(Ei+Ej),  dh = hi-hj
    //     weight = W[ci][cj];  mask = |labi-labj| > 0 (NaN-safe) ---
    const float4*        pA   = sA + tid + 1 + (jhalf << 7);
    const unsigned char* pC   = sC + tid + 1 + (jhalf << 7);
    const float*         Wrow = s_W + capped * 52;

    float acc0 = 0.0f, acc1 = 0.0f;
    #pragma unroll 8
    for (int oo = 0; oo < 127; ++oo) {
        const float4 A   = pA[oo];
        const int    cj  = pC[oo];
        const float  t2  = __fdividef(A.y, Ei + A.y);     // Ej/(Ei+Ej)
        const float  lg  = __log2f(Gi + A.x);
        const float  dh  = hi - A.z;
        const float  bce = fmaf(dh, t2, fmaf(lg, LN2F, nhi));
        const float  dl  = labi - A.w;                    // NaN if either invalid
        const float  wv  = Wrow[cj];
        const float  w   = (fabsf(dl) > 0.0f) ? wv : 0.0f;
        if (oo & 1) acc1 = fmaf(bce, w, acc1);
        else        acc0 = fmaf(bce, w, acc0);
    }
    {   // final offset (128 or 256); offset 256 double-covered -> gate tid<256
        const float4 A   = pA[127];
        const int    cj  = pC[127];
        const bool   gate = (jhalf == 0) | (tid < 256);
        const float  t2  = __fdividef(A.y, Ei + A.y);
        const float  lg  = __log2f(Gi + A.x);
        const float  dh  = hi - A.z;
        const float  bce = fmaf(dh, t2, fmaf(lg, LN2F, nhi));
        const float  dl  = labi - A.w;
        const float  wv  = Wrow[cj];
        const float  w   = (gate && fabsf(dl) > 0.0f) ? wv : 0.0f;
        acc0 = fmaf(bce, w, acc0);
    }
    float acc = acc0 + acc1;

    // --- deterministic block reduce + fused final reduce ---
    #pragma unroll
    for (int o = 16; o; o >>= 1) acc += __shfl_down_sync(0xffffffffu, acc, o);
    if (lane == 0) s_red[tid >> 5] = acc;
    __syncthreads();
    if (tid < 16) {
        float v = s_red[tid];
        #pragma unroll
        for (int o = 8; o; o >>= 1) v += __shfl_down_sync(0xffffu, v, o);
        if (tid == 0) {
            g_partial[blockIdx.x] = v * idcg * (1.0f / (float)BATCH);
            __threadfence();
            unsigned int old = atomicInc(&g_count, NBLK - 1);  // wraps -> replay-safe
            s_last = (old == NBLK - 1);
        }
    }
    __syncthreads();

    if (s_last) {
        __threadfence();
        if (tid < NBLK) {
            float v = ((volatile float*)g_partial)[tid];
            #pragma unroll
            for (int o = 16; o; o >>= 1) v += __shfl_down_sync(0xffffffffu, v, o);
            if (lane == 0) s_red[tid >> 5] = v;
        }
        __syncthreads();
        if (tid == 0) {
            float tot = 0.0f;
            #pragma unroll
            for (int w2 = 0; w2 < NBLK / 32; ++w2) tot += s_red[w2];
            out[0] = tot;
        }
    }
}

extern "C" void kernel_launch(void* const* d_in, const int* in_sizes, int n_in,
                              void* d_out, int out_size) {
    const float* logits = (const float*)d_in[0];
    const float* labels = (const float*)d_in[1];
    float* out = (float*)d_out;
    (void)in_sizes; (void)n_in; (void)out_size;

    rank_loss_main<<<NBLK, THREADS>>>(logits, labels, out);
}

// round 7
// speedup vs baseline: 1.3902x; 1.2912x over previous
#include <cuda_runtime.h>
#include <math.h>

#define BATCH   64
#define NLIST   512
#define THREADS 512
#define NBLK    128            // 2 blocks per row (offset-halves)

#define LOG_EPS (-23.025850929940457f)
#define LN2F    0.6931471805599453f

// 1/log1p(k) for k=0..52 (k=0 unused)
__constant__ float C_IL[53] = {
    0.0f,        1.44269504f, 0.91023923f, 0.72134752f, 0.62133493f,
    0.55811063f, 0.51389834f, 0.48089835f, 0.45511961f, 0.43429448f,
    0.41703239f, 0.40242960f, 0.38987124f, 0.37892269f, 0.36926938f,
    0.36067376f, 0.35295525f, 0.34597526f, 0.33962297f, 0.33380821f,
    0.32845724f, 0.32351538f, 0.31892891f, 0.31465802f, 0.31066747f,
    0.30692762f, 0.30341308f, 0.30010212f, 0.29697521f, 0.29401538f,
    0.29120814f, 0.28853901f, 0.28599983f, 0.28357871f, 0.28126653f,
    0.27905531f, 0.27693789f, 0.27490773f, 0.27295812f, 0.27108450f,
    0.26928330f, 0.26754748f, 0.26587369f, 0.26425870f, 0.26269878f,
    0.26119069f, 0.25973142f, 0.25831873f, 0.25694924f, 0.25562222f,
    0.25433417f, 0.25308478f, 0.25187249f
};

__device__ float        g_partial[NBLK];
__device__ unsigned int g_count = 0;

__global__ __launch_bounds__(THREADS)
void rank_loss_main(const float* __restrict__ logits,
                    const float* __restrict__ labels,
                    float* __restrict__ out) {
    __shared__ float  s_sl[NLIST];        // masked logits (rank phase, broadcast)
    __shared__ float4 sA[NLIST + 256];    // {Gj, Ej, hj, labj(NaN if invalid)} + mirror
    __shared__ float  sBp[NLIST + 256];   // qd with capped packed in low 8 mantissa bits
    __shared__ float  s_rel[52 * 32];     // replicated: [cd*32 + lane] -> bank==lane
    __shared__ float  s_red[16];
    __shared__ bool   s_last;

    const int tid   = threadIdx.x;
    const int lane  = tid & 31;
    const int b     = blockIdx.x >> 1;
    const int jhalf = blockIdx.x & 1;

    // --- replicated rel LUT from constant literals (no runtime log1p) ---
    for (int idx = tid; idx < 52 * 32; idx += THREADS) {
        const int rd = idx >> 5;
        s_rel[idx] = rd ? 0.75f * fabsf(C_IL[rd] - C_IL[rd + 1]) : 0.0f;
    }

    // --- per-element load / masking ---
    const float g_raw   = logits[b * NLIST + tid];
    const float lab_raw = labels[b * NLIST + tid];
    const bool  valid   = lab_raw > -1000.0f;
    const float lab     = valid ? lab_raw : 0.0f;
    const float g       = valid ? g_raw : LOG_EPS;
    s_sl[tid] = g;
    __syncthreads();

    // --- rank = 1 + #{slj > sli}; ties only among the invalid cluster (capped=51,
    //     disc=0 either way, and those appear only in masked pairs) -> exact ---
    int c0 = 0, c1 = 0, c2 = 0, c3 = 0;
    const float4* sl4 = (const float4*)s_sl;
    #pragma unroll 8
    for (int j4 = 0; j4 < NLIST / 4; ++j4) {
        float4 v = sl4[j4];             // uniform address -> broadcast, N=1
        c0 += (v.x > g);
        c1 += (v.y > g);
        c2 += (v.z > g);
        c3 += (v.w > g);
    }
    const int rank   = 1 + c0 + c1 + c2 + c3;
    const int capped = min(rank, 51);
    const float disc = (rank <= 50) ? C_IL[rank] : 0.0f;

    // --- per-element precompute ---
    const float Gi   = __expf(0.5f * g);    // exp(logit/2)
    const float Ei   = __expf(0.5f * lab);  // exp(label/2)
    const float hi   = 0.5f * g;
    const float nhi  = -hi;
    const float qdi  = 0.25f * disc;
    const float qnan = __int_as_float(0x7fffffff);
    const float labi = valid ? lab : qnan;  // NaN -> pair inactive via |dl|>0

    const unsigned qbits = (__float_as_uint(qdi) & ~0xFFu) | (unsigned)capped;
    const float4 Av = make_float4(Gi, Ei, hi, labi);
    sA[tid]  = Av;
    sBp[tid] = __uint_as_float(qbits);
    if (tid < 256) { sA[NLIST + tid] = Av; sBp[NLIST + tid] = __uint_as_float(qbits); }
    __syncthreads();

    // --- per-row IDCG (thread 0; first 50 positions, validity via NaN sentinel) ---
    float idcg = 0.0f;
    if (tid == 0) {
        float s = 0.0f;
        #pragma unroll
        for (int p = 1; p <= 50; ++p)
            if (sA[p - 1].w < 1e30f) s += C_IL[p];   // NaN compare -> false
        idcg = (s > 0.0f) ? (1.0f / s) : 0.0f;
    }

    // --- pair body: orientation-free identity, exact for both directions:
    //     bce = ln2*lg2(Gi+Gj) - hi + dh*Ej/(Ei+Ej),  dh = hi-hj
    //     w   = rel_lut[|ci-cj|] + 0.25*|di-dj|;  mask |labi-labj|>0 (NaN-safe) ---
    const float*  relbase = s_rel + lane;
    const float4* pA = sA  + tid + 1 + (jhalf << 7);
    const float*  pB = sBp + tid + 1 + (jhalf << 7);

    auto body = [&](const float4 A, const float Bp) -> float {
        const float t2  = __fdividef(A.y, Ei + A.y);
        const float lg  = __log2f(Gi + A.x);
        const float dh  = hi - A.z;
        const float bce = fmaf(dh, t2, fmaf(lg, LN2F, nhi));
        const float dl  = labi - A.w;
        const int   cj  = (int)(__float_as_uint(Bp) & 0xFFu);
        const int   cd  = abs(capped - cj);
        float w = relbase[cd << 5] + fabsf(qdi - Bp);
        w = (fabsf(dl) > 0.0f) ? w : 0.0f;
        return bce * w;
    };

    float acc0 = 0.0f, acc1 = 0.0f, acc2 = 0.0f, acc3 = 0.0f;
    int oo = 0;
    // 4-wide staged batches: 8 LDS in flight, 4 independent compute chains
    for (; oo + 4 <= 124; oo += 4) {
        const float4 A0 = pA[oo],     A1 = pA[oo + 1];
        const float4 A2 = pA[oo + 2], A3 = pA[oo + 3];
        const float  B0 = pB[oo],     B1 = pB[oo + 1];
        const float  B2 = pB[oo + 2], B3 = pB[oo + 3];
        acc0 += body(A0, B0);
        acc1 += body(A1, B1);
        acc2 += body(A2, B2);
        acc3 += body(A3, B3);
    }
    for (; oo < 127; ++oo)            // offsets 124..126
        acc0 += body(pA[oo], pB[oo]);
    {   // final offset (128 or 256); offset 256 double-covered -> gate tid<256
        const bool gate = (jhalf == 0) | (tid < 256);
        const float v = body(pA[127], pB[127]);
        acc1 += gate ? v : 0.0f;
    }
    float acc = (acc0 + acc1) + (acc2 + acc3);

    // --- deterministic block reduce + fused final reduce ---
    #pragma unroll
    for (int o = 16; o; o >>= 1) acc += __shfl_down_sync(0xffffffffu, acc, o);
    if (lane == 0) s_red[tid >> 5] = acc;
    __syncthreads();
    if (tid < 16) {
        float v = s_red[tid];
        #pragma unroll
        for (int o = 8; o; o >>= 1) v += __shfl_down_sync(0xffffu, v, o);
        if (tid == 0) {
            g_partial[blockIdx.x] = v * idcg * (1.0f / (float)BATCH);
            __threadfence();
            unsigned int old = atomicInc(&g_count, NBLK - 1);  // wraps -> replay-safe
            s_last = (old == NBLK - 1);
        }
    }
    __syncthreads();

    if (s_last) {
        __threadfence();
        if (tid < NBLK) {
            float v = ((volatile float*)g_partial)[tid];
            #pragma unroll
            for (int o = 16; o; o >>= 1) v += __shfl_down_sync(0xffffffffu, v, o);
            if (lane == 0) s_red[tid >> 5] = v;
        }
        __syncthreads();
        if (tid == 0) {
            float tot = 0.0f;
            #pragma unroll
            for (int w2 = 0; w2 < NBLK / 32; ++w2) tot += s_red[w2];
            out[0] = tot;
        }
    }
}

extern "C" void kernel_launch(void* const* d_in, const int* in_sizes, int n_in,
                              void* d_out, int out_size) {
    const float* logits = (const float*)d_in[0];
    const float* labels = (const float*)d_in[1];
    float* out = (float*)d_out;
    (void)in_sizes; (void)n_in; (void)out_size;

    rank_loss_main<<<NBLK, THREADS>>>(logits, labels, out);
}